// round 8
// baseline (speedup 1.0000x reference)
#include <cuda_runtime.h>
#include <cuda_bf16.h>
#include <stdint.h>

// ---------------- dims ----------------
#define T_STEPS 512
#define BL      65536
#define NBLK    128

// scan smem (pitch 528 = 256 bf16 + 16B pad)
#define S_WHI 0
#define S_WLO 67584
#define S_AHI 135168
#define S_ALO 168960
#define SCAN_SMEM 202752

// gemm_x smem (pitch 272 = 128 bf16 + 16B pad)
#define X_AHI 0
#define X_ALO 34816
#define X_BHI 69632
#define X_BLO 104448
#define GX_SMEM 139264

// ---------------- scratch ----------------
__device__ __nv_bfloat16 g_Wxh[4096u * 1024u];   // Wx^T [j][k] hi
__device__ __nv_bfloat16 g_Wxl[4096u * 1024u];   // lo
__device__ __nv_bfloat16 g_Whh[4096u * 1024u];   // Wh^T [j][k] hi
__device__ __nv_bfloat16 g_Whl[4096u * 1024u];
__device__ float         g_bias[4096];
__device__ __nv_bfloat16 g_Xhi[33554432u];       // x split [32768][1024]
__device__ __nv_bfloat16 g_Xlo[33554432u];
__device__ float         g_Xg[(size_t)T_STEPS * 262144u]; // x-proj + bias [row][4096]
__device__ __nv_bfloat16 g_Hhi[2][BL];           // h [b][l] hi/lo, double buffered
__device__ __nv_bfloat16 g_Hlo[2][BL];
__device__ float         g_c[BL];
__device__ float         g_gates[2][64 * 4096];  // atomic gate accumulators, parity t&1
__device__ unsigned int  g_ctr;                  // monotonic barrier counter

// ---------------- helpers ----------------
__device__ __forceinline__ uint32_t smem_u32(const void* p) {
    uint32_t a;
    asm("{ .reg .u64 t; cvta.to.shared.u64 t, %1; cvt.u32.u64 %0, t; }" : "=r"(a) : "l"(p));
    return a;
}
__device__ __forceinline__ void ldsm4(uint32_t* r, uint32_t addr) {
    asm volatile("ldmatrix.sync.aligned.m8n8.x4.shared.b16 {%0,%1,%2,%3}, [%4];"
                 : "=r"(r[0]), "=r"(r[1]), "=r"(r[2]), "=r"(r[3]) : "r"(addr));
}
__device__ __forceinline__ void mma_bf16(float* d, const uint32_t* a, uint32_t b0, uint32_t b1) {
    asm volatile("mma.sync.aligned.m16n8k16.row.col.f32.bf16.bf16.f32 "
                 "{%0,%1,%2,%3}, {%4,%5,%6,%7}, {%8,%9}, {%0,%1,%2,%3};"
                 : "+f"(d[0]), "+f"(d[1]), "+f"(d[2]), "+f"(d[3])
                 : "r"(a[0]), "r"(a[1]), "r"(a[2]), "r"(a[3]), "r"(b0), "r"(b1));
}
__device__ __forceinline__ void redg(float* p, float v) {
    asm volatile("red.global.add.f32 [%0], %1;" :: "l"(p), "f"(v) : "memory");
}
__device__ __forceinline__ void cp16(uint32_t dst, const void* src) {
    asm volatile("cp.async.cg.shared.global [%0], [%1], 16;" :: "r"(dst), "l"(src));
}
#define CP_WAIT() asm volatile("cp.async.commit_group;\n\tcp.async.wait_group 0;" ::: "memory")

// A fragment address (row-major m16k16), pitch P bytes
__device__ __forceinline__ uint32_t addrA(uint32_t base, int P, int row0, int kbyte, int lane) {
    int arow = (lane & 7) + ((lane >> 3) & 1) * 8;
    int acol = lane >> 4;
    return base + (uint32_t)((row0 + arow) * P + acol * 16 + kbyte);
}
// B fragment address (col-major k16 x n16 via x4 -> two n8 frags), pitch P bytes
__device__ __forceinline__ uint32_t addrB(uint32_t base, int P, int col0, int kbyte, int lane) {
    int bcol = (lane & 7) + (lane >> 4) * 8;
    int bk = ((lane >> 3) & 1) * 16;
    return base + (uint32_t)((col0 + bcol) * P + kbyte + bk);
}

__device__ __forceinline__ float sigm_f(float x) { return __fdividef(1.f, 1.f + __expf(-x)); }
__device__ __forceinline__ float tanh_f(float x) { return __fdividef(2.f, 1.f + __expf(-2.f * x)) - 1.f; }

// ---------------- split grid barrier (release/acquire, monotonic counter) ----------------
__device__ __forceinline__ void bar_arrive() {
    __syncthreads();
    if (threadIdx.x == 0)
        asm volatile("red.release.gpu.add.u32 [%0], 1;" :: "l"(&g_ctr) : "memory");
}
__device__ __forceinline__ void bar_wait(unsigned int target) {
    if (threadIdx.x == 0) {
        unsigned int v;
        do {
            asm volatile("ld.acquire.gpu.u32 %0, [%1];" : "=r"(v) : "l"(&g_ctr) : "memory");
        } while (v < target);
    }
    __syncthreads();
}

// ---------------- prep ----------------
__global__ void prep_weights(const float* __restrict__ Wf, const float* __restrict__ Wi,
                             const float* __restrict__ Wo, const float* __restrict__ Wg,
                             const float* __restrict__ bf, const float* __restrict__ bi,
                             const float* __restrict__ bo, const float* __restrict__ bg) {
    unsigned st = gridDim.x * blockDim.x;
    unsigned t0 = blockIdx.x * blockDim.x + threadIdx.x;
    for (unsigned i = t0; i < 4096u * 1024u; i += st) {
        unsigned j = i >> 10, k = i & 1023;
        unsigned g = j >> 10, l = j & 1023;
        const float* W = (g == 0) ? Wf : (g == 1) ? Wi : (g == 2) ? Wo : Wg;
        float vx = W[k * 1024 + l];
        float vh = W[(1024 + k) * 1024 + l];
        __nv_bfloat16 hx = __float2bfloat16(vx);
        __nv_bfloat16 hh = __float2bfloat16(vh);
        g_Wxh[i] = hx; g_Wxl[i] = __float2bfloat16(vx - __bfloat162float(hx));
        g_Whh[i] = hh; g_Whl[i] = __float2bfloat16(vh - __bfloat162float(hh));
    }
    for (unsigned i = t0; i < 4096u; i += st) {
        unsigned g = i >> 10, l = i & 1023;
        const float* b = (g == 0) ? bf : (g == 1) ? bi : (g == 2) ? bo : bg;
        g_bias[i] = b[l];
    }
}

__global__ void split_x(const float* __restrict__ x) {
    unsigned st = gridDim.x * blockDim.x;
    for (unsigned i = blockIdx.x * blockDim.x + threadIdx.x; i < 33554432u; i += st) {
        float v = x[i];
        __nv_bfloat16 hi = __float2bfloat16(v);
        g_Xhi[i] = hi;
        g_Xlo[i] = __float2bfloat16(v - __bfloat162float(hi));
    }
}

__global__ void init_state() {
    int i = blockIdx.x * blockDim.x + threadIdx.x;
    int st = gridDim.x * blockDim.x;
    if (i == 0) g_ctr = 0;    // reset barrier counter every launch (graph replays!)
    if (i < BL) {
        g_c[i] = 0.f;
        __nv_bfloat16 z = __float2bfloat16(0.f);
        g_Hhi[0][i] = z; g_Hhi[1][i] = z;
        g_Hlo[0][i] = z; g_Hlo[1][i] = z;
    }
    for (int j = i; j < 2 * 64 * 4096; j += st) ((float*)g_gates)[j] = 0.f;
}

// ---------------- gemm_x: Xg = x @ Wx + bias ----------------
// CTA tile m128 x n128, K=1024 in 8 chunks of 128. 16 warps (4m x 4n), warp m32n32.
__global__ __launch_bounds__(512, 1) void gemm_x() {
    extern __shared__ char smraw[];
    uint32_t base = smem_u32(smraw);
    char* sm = smraw;
    const int tid = threadIdx.x, lane = tid & 31, wid = tid >> 5;
    const int wm = wid & 3, wn = wid >> 2;
    const int ntile = blockIdx.x, mtile = blockIdx.y;
    const int m0 = mtile * 128, n0 = ntile * 128;

    float acc[2][4][4];
#pragma unroll
    for (int a = 0; a < 2; a++)
#pragma unroll
        for (int b = 0; b < 4; b++)
#pragma unroll
            for (int c = 0; c < 4; c++) acc[a][b][c] = 0.f;

    for (int ch = 0; ch < 8; ch++) {
#pragma unroll
        for (int r8 = 0; r8 < 4; r8++) {
            int i = tid + r8 * 512;          // 0..2047
            int r = i >> 4, c = i & 15;
            size_t srcA = (size_t)(m0 + r) * 1024 + ch * 128 + c * 8;
            size_t srcB = (size_t)(n0 + r) * 1024 + ch * 128 + c * 8;
            uint32_t dst = (uint32_t)(r * 272 + c * 16);
            cp16(base + X_AHI + dst, g_Xhi + srcA);
            cp16(base + X_ALO + dst, g_Xlo + srcA);
            cp16(base + X_BHI + dst, g_Wxh + srcB);
            cp16(base + X_BLO + dst, g_Wxl + srcB);
        }
        CP_WAIT();
        __syncthreads();

        for (int kk = 0; kk < 8; kk++) {
            int kb = kk * 32;
            uint32_t ah[2][4], al[2][4], bh[2][4], blo[2][4];
#pragma unroll
            for (int mf = 0; mf < 2; mf++) {
                ldsm4(ah[mf], addrA(base + X_AHI, 272, wm * 32 + mf * 16, kb, lane));
                ldsm4(al[mf], addrA(base + X_ALO, 272, wm * 32 + mf * 16, kb, lane));
            }
#pragma unroll
            for (int g = 0; g < 2; g++) {
                ldsm4(bh[g],  addrB(base + X_BHI, 272, wn * 32 + g * 16, kb, lane));
                ldsm4(blo[g], addrB(base + X_BLO, 272, wn * 32 + g * 16, kb, lane));
            }
#pragma unroll
            for (int mf = 0; mf < 2; mf++)
#pragma unroll
                for (int nf = 0; nf < 4; nf++) {
                    int gg = nf >> 1, pp = (nf & 1) * 2;
                    mma_bf16(acc[mf][nf], ah[mf], bh[gg][pp], bh[gg][pp + 1]);
                    mma_bf16(acc[mf][nf], al[mf], bh[gg][pp], bh[gg][pp + 1]);
                    mma_bf16(acc[mf][nf], ah[mf], blo[gg][pp], blo[gg][pp + 1]);
                }
        }
        __syncthreads();
    }

    // epilogue: + bias -> g_Xg[row][j]
    const int g = lane >> 2, t2 = (lane & 3) * 2;
#pragma unroll
    for (int mf = 0; mf < 2; mf++) {
        int r0 = m0 + wm * 32 + mf * 16 + g;
#pragma unroll
        for (int nf = 0; nf < 4; nf++) {
            int j0 = n0 + wn * 32 + nf * 8 + t2;
            float2 bi = *(const float2*)&g_bias[j0];
            float2 v0 = {acc[mf][nf][0] + bi.x, acc[mf][nf][1] + bi.y};
            float2 v1 = {acc[mf][nf][2] + bi.x, acc[mf][nf][3] + bi.y};
            *(float2*)&g_Xg[(size_t)r0 * 4096 + j0] = v0;
            *(float2*)&g_Xg[(size_t)(r0 + 8) * 4096 + j0] = v1;
        }
    }
}

// ---------------- persistent recurrent scan ----------------
// 128 CTAs: ct = bx>>2 (j-tile of 128), ks = bx&3 (K slice of 256).
// Wh slice (hi+lo) resident in smem all 512 steps. 512 threads, 16 warps (2m x 8n),
// warp tile m32(b) x n16(j), 16 k-steps, 3 split passes. Gate sums via REDG atomics.
__global__ __launch_bounds__(512, 1) void lstm_scan(float* __restrict__ out) {
    extern __shared__ char smraw[];
    uint32_t base = smem_u32(smraw);
    char* sm = smraw;
    const int tid = threadIdx.x, lane = tid & 31, wid = tid >> 5;
    const int wm = wid & 1, wn = wid >> 1;     // wm 0..1, wn 0..7
    const int bx = blockIdx.x, ct = bx >> 2, ks = bx & 3;

    // resident Wh slice: cols j [ct*128,+128), k [ks*256,+256)
#pragma unroll
    for (int r8 = 0; r8 < 8; r8++) {
        int i = tid + r8 * 512;              // 0..4095
        int r = i >> 5, c = i & 31;
        size_t src = (size_t)(ct * 128 + r) * 1024 + ks * 256 + c * 8;
        uint32_t dst = (uint32_t)(r * 528 + c * 16);
        cp16(base + S_WHI + dst, g_Whh + src);
        cp16(base + S_WLO + dst, g_Whl + src);
    }
    CP_WAIT();
    __syncthreads();

    const int g = lane >> 2, t2 = (lane & 3) * 2;
    unsigned int nbar = 0;

    for (int t = 0; t < T_STEPS; t++) {
        const int cur = t & 1;
        const __nv_bfloat16* __restrict__ hh = g_Hhi[cur];
        const __nv_bfloat16* __restrict__ hl = g_Hlo[cur];

        // stage h tile [64 b][256 k] hi+lo via cp.async
#pragma unroll
        for (int r4 = 0; r4 < 4; r4++) {
            int i = tid + r4 * 512;          // 0..2047
            int r = i >> 5, c = i & 31;
            size_t src = (size_t)r * 1024 + ks * 256 + c * 8;
            uint32_t dst = (uint32_t)(r * 528 + c * 16);
            cp16(base + S_AHI + dst, hh + src);
            cp16(base + S_ALO + dst, hl + src);
        }
        CP_WAIT();
        __syncthreads();

        float acc[2][2][4];
#pragma unroll
        for (int a = 0; a < 2; a++)
#pragma unroll
            for (int b = 0; b < 2; b++)
#pragma unroll
                for (int c = 0; c < 4; c++) acc[a][b][c] = 0.f;

        for (int kk = 0; kk < 16; kk++) {
            int kb = kk * 32;
            uint32_t ah[2][4], al[2][4], bh[4], blo[4];
#pragma unroll
            for (int mf = 0; mf < 2; mf++) {
                ldsm4(ah[mf], addrA(base + S_AHI, 528, wm * 32 + mf * 16, kb, lane));
                ldsm4(al[mf], addrA(base + S_ALO, 528, wm * 32 + mf * 16, kb, lane));
            }
            ldsm4(bh,  addrB(base + S_WHI, 528, wn * 16, kb, lane));
            ldsm4(blo, addrB(base + S_WLO, 528, wn * 16, kb, lane));
#pragma unroll
            for (int mf = 0; mf < 2; mf++)
#pragma unroll
                for (int nf = 0; nf < 2; nf++) {
                    int pp = nf * 2;
                    mma_bf16(acc[mf][nf], ah[mf], bh[pp], bh[pp + 1]);
                    mma_bf16(acc[mf][nf], al[mf], bh[pp], bh[pp + 1]);
                    mma_bf16(acc[mf][nf], ah[mf], blo[pp], blo[pp + 1]);
                }
        }

        // accumulate gates via fire-and-forget atomics: g_gates[t&1][b][j]
        {
            float* gates = g_gates[cur];
#pragma unroll
            for (int mf = 0; mf < 2; mf++) {
                int b0 = wm * 32 + mf * 16 + g;
#pragma unroll
                for (int nf = 0; nf < 2; nf++) {
                    int j0 = ct * 128 + wn * 16 + nf * 8 + t2;
                    redg(&gates[b0 * 4096 + j0],           acc[mf][nf][0]);
                    redg(&gates[b0 * 4096 + j0 + 1],       acc[mf][nf][1]);
                    redg(&gates[(b0 + 8) * 4096 + j0],     acc[mf][nf][2]);
                    redg(&gates[(b0 + 8) * 4096 + j0 + 1], acc[mf][nf][3]);
                }
            }
        }

        bar_arrive();
        // prefetch phase-2 operands in the barrier gap (Xg const; c thread-owned)
        const int idx = bx * 512 + tid;      // exactly covers 0..65535
        const int b = idx >> 10, l = idx & 1023;
        float* ga = &g_gates[cur][(b << 12) + l];
        const float* xg = g_Xg + (size_t)(t * 64 + b) * 4096 + l;
        float x0 = xg[0], x1 = xg[1024], x2 = xg[2048], x3 = xg[3072];
        float pc = g_c[idx];
        bar_wait(++nbar * NBLK);

        // phase 2: read gates, reset for reuse at t+2, LSTM pointwise update
        float gf = ga[0] + x0;
        float gi = ga[1024] + x1;
        float go = ga[2048] + x2;
        float gg2 = ga[3072] + x3;
        ga[0] = 0.f; ga[1024] = 0.f; ga[2048] = 0.f; ga[3072] = 0.f;

        float f = sigm_f(gf);
        float i = sigm_f(gi);
        float o = sigm_f(go);
        float gv = tanh_f(gg2);

        float c = fmaf(f, pc, i * gv);
        float hn = o * tanh_f(c);

        g_c[idx] = c;
        out[(size_t)t * BL + idx] = hn;
        __nv_bfloat16 hb = __float2bfloat16(hn);
        g_Hhi[cur ^ 1][idx] = hb;
        g_Hlo[cur ^ 1][idx] = __float2bfloat16(hn - __bfloat162float(hb));

        bar_arrive();
        bar_wait(++nbar * NBLK);
    }
}

// ---------------- launch ----------------
extern "C" void kernel_launch(void* const* d_in, const int* in_sizes, int n_in,
                              void* d_out, int out_size) {
    const float* x  = (const float*)d_in[0];
    const float* Wf = (const float*)d_in[1];
    const float* bf = (const float*)d_in[2];
    const float* Wi = (const float*)d_in[3];
    const float* bi = (const float*)d_in[4];
    const float* Wo = (const float*)d_in[5];
    const float* bo = (const float*)d_in[6];
    const float* Wg = (const float*)d_in[7];
    const float* bg = (const float*)d_in[8];
    float* out = (float*)d_out;

    cudaFuncSetAttribute(gemm_x, cudaFuncAttributeMaxDynamicSharedMemorySize, GX_SMEM);
    cudaFuncSetAttribute(lstm_scan, cudaFuncAttributeMaxDynamicSharedMemorySize, SCAN_SMEM);

    prep_weights<<<512, 256>>>(Wf, Wi, Wo, Wg, bf, bi, bo, bg);
    split_x<<<1024, 256>>>(x);
    init_state<<<256, 256>>>();
    gemm_x<<<dim3(32, 256), 512, GX_SMEM>>>();
    lstm_scan<<<NBLK, 512, SCAN_SMEM>>>(out);
}

// round 9
// speedup vs baseline: 1.5530x; 1.5530x over previous
#include <cuda_runtime.h>
#include <cuda_bf16.h>
#include <stdint.h>

// ---------------- dims ----------------
#define T_STEPS 512
#define BL      65536
#define NBLK    128

// scan smem (pitch 528 = 256 bf16 + 16B pad)
#define S_WHI 0
#define S_WLO 67584
#define S_AHI 135168
#define S_ALO 168960
#define SCAN_SMEM 202752

// gemm_x smem (pitch 272 = 128 bf16 + 16B pad)
#define X_AHI 0
#define X_ALO 34816
#define X_BHI 69632
#define X_BLO 104448
#define GX_SMEM 139264

// ---------------- scratch ----------------
__device__ __nv_bfloat16 g_Wxh[4096u * 1024u];   // Wx^T [j][k] hi
__device__ __nv_bfloat16 g_Wxl[4096u * 1024u];   // lo
__device__ __nv_bfloat16 g_Whh[4096u * 1024u];   // Wh^T [j][k] hi
__device__ __nv_bfloat16 g_Whl[4096u * 1024u];
__device__ float         g_bias[4096];
__device__ __nv_bfloat16 g_Xhi[33554432u];       // x split [32768][1024]
__device__ __nv_bfloat16 g_Xlo[33554432u];
__device__ float         g_Xg[(size_t)T_STEPS * 262144u]; // x-proj + bias [row][4096]
__device__ __nv_bfloat16 g_Hhi[2][BL];           // h [b][l] hi/lo, double buffered
__device__ __nv_bfloat16 g_Hlo[2][BL];
__device__ float         g_c[BL];
__device__ float         g_part[2][4u * 64u * 4096u]; // [parity][ks][b][j]
__device__ unsigned int  g_ctr1;                 // barrier 1 (global, 128)
__device__ unsigned int  g_ctr2[2];              // barrier 2 split by producer parity (64 each)

// ---------------- helpers ----------------
__device__ __forceinline__ uint32_t smem_u32(const void* p) {
    uint32_t a;
    asm("{ .reg .u64 t; cvta.to.shared.u64 t, %1; cvt.u32.u64 %0, t; }" : "=r"(a) : "l"(p));
    return a;
}
__device__ __forceinline__ void ldsm4(uint32_t* r, uint32_t addr) {
    asm volatile("ldmatrix.sync.aligned.m8n8.x4.shared.b16 {%0,%1,%2,%3}, [%4];"
                 : "=r"(r[0]), "=r"(r[1]), "=r"(r[2]), "=r"(r[3]) : "r"(addr));
}
__device__ __forceinline__ void mma_bf16(float* d, const uint32_t* a, uint32_t b0, uint32_t b1) {
    asm volatile("mma.sync.aligned.m16n8k16.row.col.f32.bf16.bf16.f32 "
                 "{%0,%1,%2,%3}, {%4,%5,%6,%7}, {%8,%9}, {%0,%1,%2,%3};"
                 : "+f"(d[0]), "+f"(d[1]), "+f"(d[2]), "+f"(d[3])
                 : "r"(a[0]), "r"(a[1]), "r"(a[2]), "r"(a[3]), "r"(b0), "r"(b1));
}
// A fragment address (row-major m16k16), pitch P bytes
__device__ __forceinline__ uint32_t addrA(uint32_t base, int P, int row0, int kbyte, int lane) {
    int arow = (lane & 7) + ((lane >> 3) & 1) * 8;
    int acol = lane >> 4;
    return base + (uint32_t)((row0 + arow) * P + acol * 16 + kbyte);
}
// B fragment address (col-major k16 x n16 via x4 -> two n8 frags), pitch P bytes
__device__ __forceinline__ uint32_t addrB(uint32_t base, int P, int col0, int kbyte, int lane) {
    int bcol = (lane & 7) + (lane >> 4) * 8;
    int bk = ((lane >> 3) & 1) * 16;
    return base + (uint32_t)((col0 + bcol) * P + kbyte + bk);
}

__device__ __forceinline__ float sigm_f(float x) { return __fdividef(1.f, 1.f + __expf(-x)); }
__device__ __forceinline__ float tanh_f(float x) { return __fdividef(2.f, 1.f + __expf(-2.f * x)) - 1.f; }

// ---------------- split grid barriers (release/acquire, monotonic counters) ----------------
__device__ __forceinline__ void ctr_arrive(unsigned int* c) {
    __syncthreads();
    if (threadIdx.x == 0)
        asm volatile("red.release.gpu.add.u32 [%0], 1;" :: "l"(c) : "memory");
}
__device__ __forceinline__ void ctr_wait(unsigned int* c, unsigned int target) {
    if (threadIdx.x == 0) {
        unsigned int v;
        do {
            asm volatile("ld.acquire.gpu.u32 %0, [%1];" : "=r"(v) : "l"(c) : "memory");
        } while (v < target);
    }
    __syncthreads();
}

// ---------------- prep ----------------
__global__ void prep_weights(const float* __restrict__ Wf, const float* __restrict__ Wi,
                             const float* __restrict__ Wo, const float* __restrict__ Wg,
                             const float* __restrict__ bf, const float* __restrict__ bi,
                             const float* __restrict__ bo, const float* __restrict__ bg) {
    unsigned st = gridDim.x * blockDim.x;
    unsigned t0 = blockIdx.x * blockDim.x + threadIdx.x;
    for (unsigned i = t0; i < 4096u * 1024u; i += st) {
        unsigned j = i >> 10, k = i & 1023;
        unsigned g = j >> 10, l = j & 1023;
        const float* W = (g == 0) ? Wf : (g == 1) ? Wi : (g == 2) ? Wo : Wg;
        float vx = W[k * 1024 + l];
        float vh = W[(1024 + k) * 1024 + l];
        __nv_bfloat16 hx = __float2bfloat16(vx);
        __nv_bfloat16 hh = __float2bfloat16(vh);
        g_Wxh[i] = hx; g_Wxl[i] = __float2bfloat16(vx - __bfloat162float(hx));
        g_Whh[i] = hh; g_Whl[i] = __float2bfloat16(vh - __bfloat162float(hh));
    }
    for (unsigned i = t0; i < 4096u; i += st) {
        unsigned g = i >> 10, l = i & 1023;
        const float* b = (g == 0) ? bf : (g == 1) ? bi : (g == 2) ? bo : bg;
        g_bias[i] = b[l];
    }
}

__global__ void split_x(const float* __restrict__ x) {
    unsigned st = gridDim.x * blockDim.x;
    for (unsigned i = blockIdx.x * blockDim.x + threadIdx.x; i < 33554432u; i += st) {
        float v = x[i];
        __nv_bfloat16 hi = __float2bfloat16(v);
        g_Xhi[i] = hi;
        g_Xlo[i] = __float2bfloat16(v - __bfloat162float(hi));
    }
}

__global__ void init_state() {
    int i = blockIdx.x * blockDim.x + threadIdx.x;
    if (i == 0) { g_ctr1 = 0; g_ctr2[0] = 0; g_ctr2[1] = 0; }   // reset (graph replays!)
    if (i < BL) {
        g_c[i] = 0.f;
        __nv_bfloat16 z = __float2bfloat16(0.f);
        g_Hhi[0][i] = z; g_Hhi[1][i] = z;
        g_Hlo[0][i] = z; g_Hlo[1][i] = z;
    }
}

// ---------------- gemm_x: Xg = x @ Wx + bias ----------------
// CTA tile m128 x n128, K=1024 in 8 chunks of 128. 16 warps (4m x 4n), warp m32n32.
__global__ __launch_bounds__(512, 1) void gemm_x() {
    extern __shared__ char smraw[];
    uint32_t base = smem_u32(smraw);
    char* sm = smraw;
    const int tid = threadIdx.x, lane = tid & 31, wid = tid >> 5;
    const int wm = wid & 3, wn = wid >> 2;
    const int ntile = blockIdx.x, mtile = blockIdx.y;
    const int m0 = mtile * 128, n0 = ntile * 128;

    float acc[2][4][4];
#pragma unroll
    for (int a = 0; a < 2; a++)
#pragma unroll
        for (int b = 0; b < 4; b++)
#pragma unroll
            for (int c = 0; c < 4; c++) acc[a][b][c] = 0.f;

    for (int ch = 0; ch < 8; ch++) {
#pragma unroll
        for (int r8 = 0; r8 < 4; r8++) {
            int i = tid + r8 * 512;          // 0..2047
            int r = i >> 4, c = i & 15;
            size_t srcA = (size_t)(m0 + r) * 1024 + ch * 128 + c * 8;
            size_t srcB = (size_t)(n0 + r) * 1024 + ch * 128 + c * 8;
            uint32_t dst = (uint32_t)(r * 272 + c * 16);
            *(uint4*)(sm + X_AHI + dst) = *(const uint4*)(g_Xhi + srcA);
            *(uint4*)(sm + X_ALO + dst) = *(const uint4*)(g_Xlo + srcA);
            *(uint4*)(sm + X_BHI + dst) = *(const uint4*)(g_Wxh + srcB);
            *(uint4*)(sm + X_BLO + dst) = *(const uint4*)(g_Wxl + srcB);
        }
        __syncthreads();

#pragma unroll 4
        for (int kk = 0; kk < 8; kk++) {
            int kb = kk * 32;
            uint32_t ah[2][4], al[2][4], bh[2][4], blo[2][4];
#pragma unroll
            for (int mf = 0; mf < 2; mf++) {
                ldsm4(ah[mf], addrA(base + X_AHI, 272, wm * 32 + mf * 16, kb, lane));
                ldsm4(al[mf], addrA(base + X_ALO, 272, wm * 32 + mf * 16, kb, lane));
            }
#pragma unroll
            for (int g = 0; g < 2; g++) {
                ldsm4(bh[g],  addrB(base + X_BHI, 272, wn * 32 + g * 16, kb, lane));
                ldsm4(blo[g], addrB(base + X_BLO, 272, wn * 32 + g * 16, kb, lane));
            }
#pragma unroll
            for (int mf = 0; mf < 2; mf++)
#pragma unroll
                for (int nf = 0; nf < 4; nf++) {
                    int gg = nf >> 1, pp = (nf & 1) * 2;
                    mma_bf16(acc[mf][nf], ah[mf], bh[gg][pp], bh[gg][pp + 1]);
                    mma_bf16(acc[mf][nf], al[mf], bh[gg][pp], bh[gg][pp + 1]);
                    mma_bf16(acc[mf][nf], ah[mf], blo[gg][pp], blo[gg][pp + 1]);
                }
        }
        __syncthreads();
    }

    // epilogue: + bias -> g_Xg[row][j]
    const int g = lane >> 2, t2 = (lane & 3) * 2;
#pragma unroll
    for (int mf = 0; mf < 2; mf++) {
        int r0 = m0 + wm * 32 + mf * 16 + g;
#pragma unroll
        for (int nf = 0; nf < 4; nf++) {
            int j0 = n0 + wn * 32 + nf * 8 + t2;
            float2 bi = *(const float2*)&g_bias[j0];
            float2 v0 = {acc[mf][nf][0] + bi.x, acc[mf][nf][1] + bi.y};
            float2 v1 = {acc[mf][nf][2] + bi.x, acc[mf][nf][3] + bi.y};
            *(float2*)&g_Xg[(size_t)r0 * 4096 + j0] = v0;
            *(float2*)&g_Xg[(size_t)(r0 + 8) * 4096 + j0] = v1;
        }
    }
}

// ---------------- persistent recurrent scan ----------------
// 128 CTAs: ct = bx>>2 (j-tile of 128), ks = bx&3 (K slice of 256).
// Wh slice (hi+lo) resident in smem all 512 steps. CTA tile m64(b) x n128(j),
// 8 warps (2m x 4n), warp m32n32, 16 k-steps, 3 split passes.
// Partials double-buffered by parity; barrier2 split by producer parity.
__global__ __launch_bounds__(256, 1) void lstm_scan(float* __restrict__ out) {
    extern __shared__ char smraw[];
    uint32_t base = smem_u32(smraw);
    char* sm = smraw;
    const int tid = threadIdx.x, lane = tid & 31, wid = tid >> 5;
    const int wm = wid & 1, wn = wid >> 1;
    const int bx = blockIdx.x, ct = bx >> 2, ks = bx & 3;

    // resident Wh slice: cols j [ct*128,+128), k [ks*256,+256)
#pragma unroll
    for (int r16 = 0; r16 < 16; r16++) {
        int i = tid + r16 * 256;             // 0..4095
        int r = i >> 5, c = i & 31;
        size_t src = (size_t)(ct * 128 + r) * 1024 + ks * 256 + c * 8;
        uint32_t dst = (uint32_t)(r * 528 + c * 16);
        *(uint4*)(sm + S_WHI + dst) = *(const uint4*)(g_Whh + src);
        *(uint4*)(sm + S_WLO + dst) = *(const uint4*)(g_Whl + src);
    }
    __syncthreads();

    const int g = lane >> 2, t2 = (lane & 3) * 2;
    // phase-2 element ownership (fixed per thread): parity of bx selects h l-half produced
    const int my_par = bx & 1;           // producer parity for barrier 2
    const int need_par = ks >> 1;        // consumer parity for barrier 2

    for (int t = 0; t < T_STEPS; t++) {
        const int cur = t & 1;
        const __nv_bfloat16* __restrict__ hh = g_Hhi[cur];
        const __nv_bfloat16* __restrict__ hl = g_Hlo[cur];
        float* __restrict__ part = g_part[cur];

        // stage h tile [64 b][256 k]
#pragma unroll
        for (int r8 = 0; r8 < 8; r8++) {
            int i = tid + r8 * 256;          // 0..2047
            int r = i >> 5, c = i & 31;
            size_t src = (size_t)r * 1024 + ks * 256 + c * 8;
            uint32_t dst = (uint32_t)(r * 528 + c * 16);
            *(uint4*)(sm + S_AHI + dst) = *(const uint4*)(hh + src);
            *(uint4*)(sm + S_ALO + dst) = *(const uint4*)(hl + src);
        }
        __syncthreads();

        float acc[2][4][4];
#pragma unroll
        for (int a = 0; a < 2; a++)
#pragma unroll
            for (int b = 0; b < 4; b++)
#pragma unroll
                for (int c = 0; c < 4; c++) acc[a][b][c] = 0.f;

#pragma unroll 4
        for (int kk = 0; kk < 16; kk++) {
            int kb = kk * 32;
            uint32_t ah[2][4], al[2][4], bh[2][4], blo[2][4];
#pragma unroll
            for (int mf = 0; mf < 2; mf++) {
                ldsm4(ah[mf], addrA(base + S_AHI, 528, wm * 32 + mf * 16, kb, lane));
                ldsm4(al[mf], addrA(base + S_ALO, 528, wm * 32 + mf * 16, kb, lane));
            }
#pragma unroll
            for (int gg = 0; gg < 2; gg++) {
                ldsm4(bh[gg],  addrB(base + S_WHI, 528, wn * 32 + gg * 16, kb, lane));
                ldsm4(blo[gg], addrB(base + S_WLO, 528, wn * 32 + gg * 16, kb, lane));
            }
#pragma unroll
            for (int mf = 0; mf < 2; mf++)
#pragma unroll
                for (int nf = 0; nf < 4; nf++) {
                    int gg = nf >> 1, pp = (nf & 1) * 2;
                    mma_bf16(acc[mf][nf], ah[mf], bh[gg][pp], bh[gg][pp + 1]);
                    mma_bf16(acc[mf][nf], al[mf], bh[gg][pp], bh[gg][pp + 1]);
                    mma_bf16(acc[mf][nf], ah[mf], blo[gg][pp], blo[gg][pp + 1]);
                }
        }

        // write partials: part[ks][b][j]
#pragma unroll
        for (int mf = 0; mf < 2; mf++) {
            int b0 = wm * 32 + mf * 16 + g;
#pragma unroll
            for (int nf = 0; nf < 4; nf++) {
                int j0 = ct * 128 + wn * 32 + nf * 8 + t2;
                *(float2*)&part[(size_t)(ks * 64 + b0) * 4096 + j0] =
                    make_float2(acc[mf][nf][0], acc[mf][nf][1]);
                *(float2*)&part[(size_t)(ks * 64 + b0 + 8) * 4096 + j0] =
                    make_float2(acc[mf][nf][2], acc[mf][nf][3]);
            }
        }

        ctr_arrive(&g_ctr1);
        // prefetch phase-2 operands in the barrier gap (Xg const; c thread-owned)
        float pxg[2][4], pc[2];
        int pidx[2];
#pragma unroll
        for (int r2 = 0; r2 < 2; r2++) {
            int idx = bx * 512 + r2 * 256 + tid;
            pidx[r2] = idx;
            int b = idx >> 10, l = idx & 1023;
            const float* xg = g_Xg + (size_t)(t * 64 + b) * 4096 + l;
            pxg[r2][0] = xg[0];
            pxg[r2][1] = xg[1024];
            pxg[r2][2] = xg[2048];
            pxg[r2][3] = xg[3072];
            pc[r2] = g_c[idx];
        }
        ctr_wait(&g_ctr1, (unsigned)(t + 1) * NBLK);

        // phase 2: reduce partials + Xg, LSTM pointwise update
#pragma unroll
        for (int r2 = 0; r2 < 2; r2++) {
            int idx = pidx[r2];
            int b = idx >> 10, l = idx & 1023;
            int gidx = (b << 12) + l;
            float gf = pxg[r2][0], gi = pxg[r2][1], go = pxg[r2][2], gg2 = pxg[r2][3];
#pragma unroll
            for (int s = 0; s < 4; s++) {
                const float* p = part + (size_t)s * 262144 + gidx;
                gf += p[0];
                gi += p[1024];
                go += p[2048];
                gg2 += p[3072];
            }

            float f = sigm_f(gf);
            float i = sigm_f(gi);
            float o = sigm_f(go);
            float gv = tanh_f(gg2);

            float c = fmaf(f, pc[r2], i * gv);
            float hn = o * tanh_f(c);

            g_c[idx] = c;
            out[(size_t)t * BL + idx] = hn;
            __nv_bfloat16 hb = __float2bfloat16(hn);
            g_Hhi[cur ^ 1][idx] = hb;
            g_Hlo[cur ^ 1][idx] = __float2bfloat16(hn - __bfloat162float(hb));
        }

        // barrier 2: split by producer parity; consumer only needs its h-half producers
        ctr_arrive(&g_ctr2[my_par]);
        ctr_wait(&g_ctr2[need_par], (unsigned)(t + 1) * 64);
    }
}

// ---------------- launch ----------------
extern "C" void kernel_launch(void* const* d_in, const int* in_sizes, int n_in,
                              void* d_out, int out_size) {
    const float* x  = (const float*)d_in[0];
    const float* Wf = (const float*)d_in[1];
    const float* bf = (const float*)d_in[2];
    const float* Wi = (const float*)d_in[3];
    const float* bi = (const float*)d_in[4];
    const float* Wo = (const float*)d_in[5];
    const float* bo = (const float*)d_in[6];
    const float* Wg = (const float*)d_in[7];
    const float* bg = (const float*)d_in[8];
    float* out = (float*)d_out;

    cudaFuncSetAttribute(gemm_x, cudaFuncAttributeMaxDynamicSharedMemorySize, GX_SMEM);
    cudaFuncSetAttribute(lstm_scan, cudaFuncAttributeMaxDynamicSharedMemorySize, SCAN_SMEM);

    prep_weights<<<512, 256>>>(Wf, Wi, Wo, Wg, bf, bi, bo, bg);
    split_x<<<1024, 256>>>(x);
    init_state<<<256, 256>>>();
    gemm_x<<<dim3(32, 256), 512, GX_SMEM>>>();
    lstm_scan<<<NBLK, 256, SCAN_SMEM>>>(out);
}

// round 11
// speedup vs baseline: 1.9453x; 1.2526x over previous
#include <cuda_runtime.h>
#include <cuda_fp16.h>
#include <stdint.h>

// ---------------- dims ----------------
#define T_STEPS 512
#define BL      65536
#define NBLK    128

// scan smem (pitch 528 = 256 fp16 + 16B pad)
#define S_WH  0                     // W single fp16, 128 rows x 528
#define S_AHI 67584                 // h hi, 64 rows x 528
#define S_ALO 101376                // h lo
#define SCAN_SMEM 135168

// gemm_x smem (pitch 272 = 128 fp16 + 16B pad)
#define X_AHI 0
#define X_ALO 34816
#define X_BH  69632
#define GX_SMEM 104448

// ---------------- scratch ----------------
__device__ __half g_Wx[4096u * 1024u];           // Wx^T [j][k] single fp16
__device__ __half g_Wh[4096u * 1024u];           // Wh^T [j][k] single fp16
__device__ float  g_bias[4096];
__device__ __half g_Xhi[33554432u];              // x split [32768][1024]
__device__ __half g_Xlo[33554432u];
__device__ float  g_Xg[(size_t)T_STEPS * 262144u]; // x-proj + bias [row][4096]
__device__ __half g_Hhi[2][BL];                  // h [b][l] hi/lo, double buffered
__device__ __half g_Hlo[2][BL];
__device__ float  g_c[BL];
__device__ float  g_part[4u * 64u * 4096u];      // [ks][b][j]
__device__ unsigned int g_ctr;                   // monotonic barrier counter

// ---------------- helpers ----------------
__device__ __forceinline__ uint32_t smem_u32(const void* p) {
    uint32_t a;
    asm("{ .reg .u64 t; cvta.to.shared.u64 t, %1; cvt.u32.u64 %0, t; }" : "=r"(a) : "l"(p));
    return a;
}
__device__ __forceinline__ void ldsm4(uint32_t* r, uint32_t addr) {
    asm volatile("ldmatrix.sync.aligned.m8n8.x4.shared.b16 {%0,%1,%2,%3}, [%4];"
                 : "=r"(r[0]), "=r"(r[1]), "=r"(r[2]), "=r"(r[3]) : "r"(addr));
}
__device__ __forceinline__ void mma_f16(float* d, const uint32_t* a, uint32_t b0, uint32_t b1) {
    asm volatile("mma.sync.aligned.m16n8k16.row.col.f32.f16.f16.f32 "
                 "{%0,%1,%2,%3}, {%4,%5,%6,%7}, {%8,%9}, {%0,%1,%2,%3};"
                 : "+f"(d[0]), "+f"(d[1]), "+f"(d[2]), "+f"(d[3])
                 : "r"(a[0]), "r"(a[1]), "r"(a[2]), "r"(a[3]), "r"(b0), "r"(b1));
}
// A fragment address (row-major m16k16), pitch P bytes
__device__ __forceinline__ uint32_t addrA(uint32_t base, int P, int row0, int kbyte, int lane) {
    int arow = (lane & 7) + ((lane >> 3) & 1) * 8;
    int acol = lane >> 4;
    return base + (uint32_t)((row0 + arow) * P + acol * 16 + kbyte);
}
// B fragment address (col-major k16 x n16 via x4 -> two n8 frags), pitch P bytes
__device__ __forceinline__ uint32_t addrB(uint32_t base, int P, int col0, int kbyte, int lane) {
    int bcol = (lane & 7) + (lane >> 4) * 8;
    int bk = ((lane >> 3) & 1) * 16;
    return base + (uint32_t)((col0 + bcol) * P + kbyte + bk);
}

__device__ __forceinline__ float sigm_f(float x) { return __fdividef(1.f, 1.f + __expf(-x)); }
__device__ __forceinline__ float tanh_f(float x) { return __fdividef(2.f, 1.f + __expf(-2.f * x)) - 1.f; }

// ---------------- split grid barrier (release/acquire, monotonic counter) ----------------
__device__ __forceinline__ void bar_arrive() {
    __syncthreads();
    if (threadIdx.x == 0)
        asm volatile("red.release.gpu.add.u32 [%0], 1;" :: "l"(&g_ctr) : "memory");
}
__device__ __forceinline__ void bar_wait(unsigned int target) {
    if (threadIdx.x == 0) {
        unsigned int v;
        do {
            asm volatile("ld.acquire.gpu.u32 %0, [%1];" : "=r"(v) : "l"(&g_ctr) : "memory");
        } while (v < target);
    }
    __syncthreads();
}

// ---------------- prep ----------------
__global__ void prep_weights(const float* __restrict__ Wf, const float* __restrict__ Wi,
                             const float* __restrict__ Wo, const float* __restrict__ Wg,
                             const float* __restrict__ bf, const float* __restrict__ bi,
                             const float* __restrict__ bo, const float* __restrict__ bg) {
    unsigned st = gridDim.x * blockDim.x;
    unsigned t0 = blockIdx.x * blockDim.x + threadIdx.x;
    for (unsigned i = t0; i < 4096u * 1024u; i += st) {
        unsigned j = i >> 10, k = i & 1023;
        unsigned g = j >> 10, l = j & 1023;
        const float* W = (g == 0) ? Wf : (g == 1) ? Wi : (g == 2) ? Wo : Wg;
        g_Wx[i] = __float2half(W[k * 1024 + l]);
        g_Wh[i] = __float2half(W[(1024 + k) * 1024 + l]);
    }
    for (unsigned i = t0; i < 4096u; i += st) {
        unsigned g = i >> 10, l = i & 1023;
        const float* b = (g == 0) ? bf : (g == 1) ? bi : (g == 2) ? bo : bg;
        g_bias[i] = b[l];
    }
}

__global__ void split_x(const float* __restrict__ x) {
    unsigned st = gridDim.x * blockDim.x;
    for (unsigned i = blockIdx.x * blockDim.x + threadIdx.x; i < 33554432u; i += st) {
        float v = x[i];
        __half hi = __float2half(v);
        g_Xhi[i] = hi;
        g_Xlo[i] = __float2half(v - __half2float(hi));
    }
}

__global__ void init_state() {
    int i = blockIdx.x * blockDim.x + threadIdx.x;
    if (i == 0) g_ctr = 0;    // reset barrier counter every launch (graph replays!)
    if (i < BL) {
        g_c[i] = 0.f;
        __half z = __float2half(0.f);
        g_Hhi[0][i] = z; g_Hhi[1][i] = z;
        g_Hlo[0][i] = z; g_Hlo[1][i] = z;
    }
}

// ---------------- gemm_x: Xg = x @ Wx + bias ----------------
// CTA tile m128 x n128, K=1024 in 8 chunks of 128. 16 warps (4m x 4n), warp m32n32.
// A = x rows (hi+lo fp16), B = Wx cols (single fp16). 2 MMA passes.
__global__ __launch_bounds__(512, 1) void gemm_x() {
    extern __shared__ char smraw[];
    uint32_t base = smem_u32(smraw);
    char* sm = smraw;
    const int tid = threadIdx.x, lane = tid & 31, wid = tid >> 5;
    const int wm = wid & 3, wn = wid >> 2;
    const int ntile = blockIdx.x, mtile = blockIdx.y;
    const int m0 = mtile * 128, n0 = ntile * 128;

    float acc[2][4][4];
#pragma unroll
    for (int a = 0; a < 2; a++)
#pragma unroll
        for (int b = 0; b < 4; b++)
#pragma unroll
            for (int c = 0; c < 4; c++) acc[a][b][c] = 0.f;

    for (int ch = 0; ch < 8; ch++) {
#pragma unroll
        for (int r8 = 0; r8 < 4; r8++) {
            int i = tid + r8 * 512;          // 0..2047
            int r = i >> 4, c = i & 15;
            size_t srcA = (size_t)(m0 + r) * 1024 + ch * 128 + c * 8;
            size_t srcB = (size_t)(n0 + r) * 1024 + ch * 128 + c * 8;
            uint32_t dst = (uint32_t)(r * 272 + c * 16);
            *(uint4*)(sm + X_AHI + dst) = *(const uint4*)(g_Xhi + srcA);
            *(uint4*)(sm + X_ALO + dst) = *(const uint4*)(g_Xlo + srcA);
            *(uint4*)(sm + X_BH + dst) = *(const uint4*)(g_Wx + srcB);
        }
        __syncthreads();

        for (int kk = 0; kk < 8; kk++) {
            int kb = kk * 32;
            uint32_t ah[2][4], al[2][4], bh[2][4];
#pragma unroll
            for (int mf = 0; mf < 2; mf++) {
                ldsm4(ah[mf], addrA(base + X_AHI, 272, wm * 32 + mf * 16, kb, lane));
                ldsm4(al[mf], addrA(base + X_ALO, 272, wm * 32 + mf * 16, kb, lane));
            }
#pragma unroll
            for (int g = 0; g < 2; g++)
                ldsm4(bh[g], addrB(base + X_BH, 272, wn * 32 + g * 16, kb, lane));
#pragma unroll
            for (int mf = 0; mf < 2; mf++)
#pragma unroll
                for (int nf = 0; nf < 4; nf++) {
                    int gg = nf >> 1, pp = (nf & 1) * 2;
                    mma_f16(acc[mf][nf], ah[mf], bh[gg][pp], bh[gg][pp + 1]);
                    mma_f16(acc[mf][nf], al[mf], bh[gg][pp], bh[gg][pp + 1]);
                }
        }
        __syncthreads();
    }

    // epilogue: + bias -> g_Xg[row][j]
    const int g = lane >> 2, t2 = (lane & 3) * 2;
#pragma unroll
    for (int mf = 0; mf < 2; mf++) {
        int r0 = m0 + wm * 32 + mf * 16 + g;
#pragma unroll
        for (int nf = 0; nf < 4; nf++) {
            int j0 = n0 + wn * 32 + nf * 8 + t2;
            float2 bi = *(const float2*)&g_bias[j0];
            float2 v0 = {acc[mf][nf][0] + bi.x, acc[mf][nf][1] + bi.y};
            float2 v1 = {acc[mf][nf][2] + bi.x, acc[mf][nf][3] + bi.y};
            *(float2*)&g_Xg[(size_t)r0 * 4096 + j0] = v0;
            *(float2*)&g_Xg[(size_t)(r0 + 8) * 4096 + j0] = v1;
        }
    }
}

// ---------------- persistent recurrent scan ----------------
// 128 CTAs: ct = bx>>2 (j-tile of 128), ks = bx&3 (K slice of 256).
// Wh slice (single fp16) resident in smem all 512 steps. CTA tile m64(b) x n128(j),
// 8 warps (2m x 4n), warp m32n32, 16 k-steps, 2 split passes.
__global__ __launch_bounds__(256, 1) void lstm_scan(float* __restrict__ out) {
    extern __shared__ char smraw[];
    uint32_t base = smem_u32(smraw);
    char* sm = smraw;
    const int tid = threadIdx.x, lane = tid & 31, wid = tid >> 5;
    const int wm = wid & 1, wn = wid >> 1;
    const int bx = blockIdx.x, ct = bx >> 2, ks = bx & 3;

    // resident Wh slice: cols j [ct*128,+128), k [ks*256,+256)
#pragma unroll
    for (int r16 = 0; r16 < 16; r16++) {
        int i = tid + r16 * 256;             // 0..4095
        int r = i >> 5, c = i & 31;
        size_t src = (size_t)(ct * 128 + r) * 1024 + ks * 256 + c * 8;
        uint32_t dst = (uint32_t)(r * 528 + c * 16);
        *(uint4*)(sm + S_WH + dst) = *(const uint4*)(g_Wh + src);
    }
    __syncthreads();

    const int g = lane >> 2, t2 = (lane & 3) * 2;
    unsigned int nbar = 0;

    for (int t = 0; t < T_STEPS; t++) {
        const int cur = t & 1;
        const __half* __restrict__ hh = g_Hhi[cur];
        const __half* __restrict__ hl = g_Hlo[cur];

        // stage h tile [64 b][256 k] hi+lo
#pragma unroll
        for (int r8 = 0; r8 < 8; r8++) {
            int i = tid + r8 * 256;          // 0..2047
            int r = i >> 5, c = i & 31;
            size_t src = (size_t)r * 1024 + ks * 256 + c * 8;
            uint32_t dst = (uint32_t)(r * 528 + c * 16);
            *(uint4*)(sm + S_AHI + dst) = *(const uint4*)(hh + src);
            *(uint4*)(sm + S_ALO + dst) = *(const uint4*)(hl + src);
        }
        __syncthreads();

        float acc[2][4][4];
#pragma unroll
        for (int a = 0; a < 2; a++)
#pragma unroll
            for (int b = 0; b < 4; b++)
#pragma unroll
                for (int c = 0; c < 4; c++) acc[a][b][c] = 0.f;

        for (int kk = 0; kk < 16; kk++) {
            int kb = kk * 32;
            uint32_t ah[2][4], al[2][4], bh[2][4];
#pragma unroll
            for (int mf = 0; mf < 2; mf++) {
                ldsm4(ah[mf], addrA(base + S_AHI, 528, wm * 32 + mf * 16, kb, lane));
                ldsm4(al[mf], addrA(base + S_ALO, 528, wm * 32 + mf * 16, kb, lane));
            }
#pragma unroll
            for (int gg = 0; gg < 2; gg++)
                ldsm4(bh[gg], addrB(base + S_WH, 528, wn * 32 + gg * 16, kb, lane));
#pragma unroll
            for (int mf = 0; mf < 2; mf++)
#pragma unroll
                for (int nf = 0; nf < 4; nf++) {
                    int gg = nf >> 1, pp = (nf & 1) * 2;
                    mma_f16(acc[mf][nf], ah[mf], bh[gg][pp], bh[gg][pp + 1]);
                    mma_f16(acc[mf][nf], al[mf], bh[gg][pp], bh[gg][pp + 1]);
                }
        }

        // write partials: g_part[ks][b][j]
#pragma unroll
        for (int mf = 0; mf < 2; mf++) {
            int b0 = wm * 32 + mf * 16 + g;
#pragma unroll
            for (int nf = 0; nf < 4; nf++) {
                int j0 = ct * 128 + wn * 32 + nf * 8 + t2;
                *(float2*)&g_part[(size_t)(ks * 64 + b0) * 4096 + j0] =
                    make_float2(acc[mf][nf][0], acc[mf][nf][1]);
                *(float2*)&g_part[(size_t)(ks * 64 + b0 + 8) * 4096 + j0] =
                    make_float2(acc[mf][nf][2], acc[mf][nf][3]);
            }
        }

        bar_arrive();
        // prefetch phase-2 operands in the barrier gap (Xg const; c thread-owned)
        float pxg[2][4], pc[2];
        int pidx[2];
#pragma unroll
        for (int r2 = 0; r2 < 2; r2++) {
            int idx = bx * 512 + r2 * 256 + tid;
            pidx[r2] = idx;
            int b = idx >> 10, l = idx & 1023;
            const float* xg = g_Xg + (size_t)(t * 64 + b) * 4096 + l;
            pxg[r2][0] = xg[0];
            pxg[r2][1] = xg[1024];
            pxg[r2][2] = xg[2048];
            pxg[r2][3] = xg[3072];
            pc[r2] = g_c[idx];
        }
        bar_wait(++nbar * NBLK);

        // phase 2: reduce partials + Xg, LSTM pointwise update
#pragma unroll
        for (int r2 = 0; r2 < 2; r2++) {
            int idx = pidx[r2];
            int b = idx >> 10, l = idx & 1023;
            int gidx = (b << 12) + l;
            float gf = pxg[r2][0], gi = pxg[r2][1], go = pxg[r2][2], gg2 = pxg[r2][3];
#pragma unroll
            for (int s = 0; s < 4; s++) {
                const float* p = g_part + (size_t)s * 262144 + gidx;
                gf += p[0];
                gi += p[1024];
                go += p[2048];
                gg2 += p[3072];
            }

            float f = sigm_f(gf);
            float i = sigm_f(gi);
            float o = sigm_f(go);
            float gv = tanh_f(gg2);

            float c = fmaf(f, pc[r2], i * gv);
            float hn = o * tanh_f(c);

            g_c[idx] = c;
            out[(size_t)t * BL + idx] = hn;
            __half hb = __float2half(hn);
            g_Hhi[cur ^ 1][idx] = hb;
            g_Hlo[cur ^ 1][idx] = __float2half(hn - __half2float(hb));
        }

        bar_arrive();
        bar_wait(++nbar * NBLK);
    }
}

// ---------------- launch ----------------
extern "C" void kernel_launch(void* const* d_in, const int* in_sizes, int n_in,
                              void* d_out, int out_size) {
    const float* x  = (const float*)d_in[0];
    const float* Wf = (const float*)d_in[1];
    const float* bf = (const float*)d_in[2];
    const float* Wi = (const float*)d_in[3];
    const float* bi = (const float*)d_in[4];
    const float* Wo = (const float*)d_in[5];
    const float* bo = (const float*)d_in[6];
    const float* Wg = (const float*)d_in[7];
    const float* bg = (const float*)d_in[8];
    float* out = (float*)d_out;

    cudaFuncSetAttribute(gemm_x, cudaFuncAttributeMaxDynamicSharedMemorySize, GX_SMEM);
    cudaFuncSetAttribute(lstm_scan, cudaFuncAttributeMaxDynamicSharedMemorySize, SCAN_SMEM);

    prep_weights<<<512, 256>>>(Wf, Wi, Wo, Wg, bf, bi, bo, bg);
    split_x<<<1024, 256>>>(x);
    init_state<<<256, 256>>>();
    gemm_x<<<dim3(32, 256), 512, GX_SMEM>>>();
    lstm_scan<<<NBLK, 256, SCAN_SMEM>>>(out);
}

// round 12
// speedup vs baseline: 2.2070x; 1.1345x over previous
#include <cuda_runtime.h>
#include <cuda_fp16.h>
#include <stdint.h>

// ---------------- dims ----------------
#define T_STEPS 512
#define BL      65536
#define NBLK    128

// scan smem (pitch 528 = 256 fp16 + 16B pad)
#define S_WH  0                     // W single fp16, 128 rows x 528
#define S_AHI 67584                 // h single fp16, 64 rows x 528
#define SCAN_SMEM 101376

// gemm_x smem (pitch 272 = 128 fp16 + 16B pad)
#define X_AHI 0
#define X_ALO 34816
#define X_BH  69632
#define GX_SMEM 104448

// ---------------- scratch ----------------
__device__ __half g_Wx[4096u * 1024u];           // Wx^T [j][k] single fp16
__device__ __half g_Wh[4096u * 1024u];           // Wh^T [j][k] single fp16
__device__ float  g_bias[4096];
__device__ __half g_Xhi[33554432u];              // x split [32768][1024]
__device__ __half g_Xlo[33554432u];
__device__ float  g_Xg[(size_t)T_STEPS * 262144u]; // x-proj + bias [row][4096]
__device__ __half g_Hhi[2][BL];                  // h [b][l], double buffered (single fp16)
__device__ float  g_c[BL];
__device__ float  g_part[4u * 64u * 4096u];      // [ks][b][j]
__device__ unsigned int g_ctr;                   // monotonic barrier counter

// ---------------- helpers ----------------
__device__ __forceinline__ uint32_t smem_u32(const void* p) {
    uint32_t a;
    asm("{ .reg .u64 t; cvta.to.shared.u64 t, %1; cvt.u32.u64 %0, t; }" : "=r"(a) : "l"(p));
    return a;
}
__device__ __forceinline__ void ldsm4(uint32_t* r, uint32_t addr) {
    asm volatile("ldmatrix.sync.aligned.m8n8.x4.shared.b16 {%0,%1,%2,%3}, [%4];"
                 : "=r"(r[0]), "=r"(r[1]), "=r"(r[2]), "=r"(r[3]) : "r"(addr));
}
__device__ __forceinline__ void mma_f16(float* d, const uint32_t* a, uint32_t b0, uint32_t b1) {
    asm volatile("mma.sync.aligned.m16n8k16.row.col.f32.f16.f16.f32 "
                 "{%0,%1,%2,%3}, {%4,%5,%6,%7}, {%8,%9}, {%0,%1,%2,%3};"
                 : "+f"(d[0]), "+f"(d[1]), "+f"(d[2]), "+f"(d[3])
                 : "r"(a[0]), "r"(a[1]), "r"(a[2]), "r"(a[3]), "r"(b0), "r"(b1));
}
// A fragment address (row-major m16k16), pitch P bytes
__device__ __forceinline__ uint32_t addrA(uint32_t base, int P, int row0, int kbyte, int lane) {
    int arow = (lane & 7) + ((lane >> 3) & 1) * 8;
    int acol = lane >> 4;
    return base + (uint32_t)((row0 + arow) * P + acol * 16 + kbyte);
}
// B fragment address (col-major k16 x n16 via x4 -> two n8 frags), pitch P bytes
__device__ __forceinline__ uint32_t addrB(uint32_t base, int P, int col0, int kbyte, int lane) {
    int bcol = (lane & 7) + (lane >> 4) * 8;
    int bk = ((lane >> 3) & 1) * 16;
    return base + (uint32_t)((col0 + bcol) * P + kbyte + bk);
}

__device__ __forceinline__ float sigm_f(float x) { return __fdividef(1.f, 1.f + __expf(-x)); }
__device__ __forceinline__ float tanh_f(float x) { return __fdividef(2.f, 1.f + __expf(-2.f * x)) - 1.f; }

// ---------------- split grid barrier (release/acquire, monotonic counter) ----------------
__device__ __forceinline__ void bar_arrive() {
    __syncthreads();
    if (threadIdx.x == 0)
        asm volatile("red.release.gpu.add.u32 [%0], 1;" :: "l"(&g_ctr) : "memory");
}
__device__ __forceinline__ void bar_wait(unsigned int target) {
    if (threadIdx.x == 0) {
        unsigned int v;
        do {
            asm volatile("ld.acquire.gpu.u32 %0, [%1];" : "=r"(v) : "l"(&g_ctr) : "memory");
        } while (v < target);
    }
    __syncthreads();
}

// ---------------- prep ----------------
__global__ void prep_weights(const float* __restrict__ Wf, const float* __restrict__ Wi,
                             const float* __restrict__ Wo, const float* __restrict__ Wg,
                             const float* __restrict__ bf, const float* __restrict__ bi,
                             const float* __restrict__ bo, const float* __restrict__ bg) {
    unsigned st = gridDim.x * blockDim.x;
    unsigned t0 = blockIdx.x * blockDim.x + threadIdx.x;
    for (unsigned i = t0; i < 4096u * 1024u; i += st) {
        unsigned j = i >> 10, k = i & 1023;
        unsigned g = j >> 10, l = j & 1023;
        const float* W = (g == 0) ? Wf : (g == 1) ? Wi : (g == 2) ? Wo : Wg;
        g_Wx[i] = __float2half(W[k * 1024 + l]);
        g_Wh[i] = __float2half(W[(1024 + k) * 1024 + l]);
    }
    for (unsigned i = t0; i < 4096u; i += st) {
        unsigned g = i >> 10, l = i & 1023;
        const float* b = (g == 0) ? bf : (g == 1) ? bi : (g == 2) ? bo : bg;
        g_bias[i] = b[l];
    }
}

__global__ void split_x(const float* __restrict__ x) {
    unsigned st = gridDim.x * blockDim.x;
    for (unsigned i = blockIdx.x * blockDim.x + threadIdx.x; i < 33554432u; i += st) {
        float v = x[i];
        __half hi = __float2half(v);
        g_Xhi[i] = hi;
        g_Xlo[i] = __float2half(v - __half2float(hi));
    }
}

__global__ void init_state() {
    int i = blockIdx.x * blockDim.x + threadIdx.x;
    if (i == 0) g_ctr = 0;    // reset barrier counter every launch (graph replays!)
    if (i < BL) {
        g_c[i] = 0.f;
        __half z = __float2half(0.f);
        g_Hhi[0][i] = z; g_Hhi[1][i] = z;
    }
}

// ---------------- gemm_x: Xg = x @ Wx + bias ----------------
// CTA tile m128 x n128, K=1024 in 8 chunks of 128. 16 warps (4m x 4n), warp m32n32.
// A = x rows (hi+lo fp16), B = Wx cols (single fp16). 2 MMA passes.
__global__ __launch_bounds__(512, 1) void gemm_x() {
    extern __shared__ char smraw[];
    uint32_t base = smem_u32(smraw);
    char* sm = smraw;
    const int tid = threadIdx.x, lane = tid & 31, wid = tid >> 5;
    const int wm = wid & 3, wn = wid >> 2;
    const int ntile = blockIdx.x, mtile = blockIdx.y;
    const int m0 = mtile * 128, n0 = ntile * 128;

    float acc[2][4][4];
#pragma unroll
    for (int a = 0; a < 2; a++)
#pragma unroll
        for (int b = 0; b < 4; b++)
#pragma unroll
            for (int c = 0; c < 4; c++) acc[a][b][c] = 0.f;

    for (int ch = 0; ch < 8; ch++) {
#pragma unroll
        for (int r8 = 0; r8 < 4; r8++) {
            int i = tid + r8 * 512;          // 0..2047
            int r = i >> 4, c = i & 15;
            size_t srcA = (size_t)(m0 + r) * 1024 + ch * 128 + c * 8;
            size_t srcB = (size_t)(n0 + r) * 1024 + ch * 128 + c * 8;
            uint32_t dst = (uint32_t)(r * 272 + c * 16);
            *(uint4*)(sm + X_AHI + dst) = *(const uint4*)(g_Xhi + srcA);
            *(uint4*)(sm + X_ALO + dst) = *(const uint4*)(g_Xlo + srcA);
            *(uint4*)(sm + X_BH + dst) = *(const uint4*)(g_Wx + srcB);
        }
        __syncthreads();

        for (int kk = 0; kk < 8; kk++) {
            int kb = kk * 32;
            uint32_t ah[2][4], al[2][4], bh[2][4];
#pragma unroll
            for (int mf = 0; mf < 2; mf++) {
                ldsm4(ah[mf], addrA(base + X_AHI, 272, wm * 32 + mf * 16, kb, lane));
                ldsm4(al[mf], addrA(base + X_ALO, 272, wm * 32 + mf * 16, kb, lane));
            }
#pragma unroll
            for (int g = 0; g < 2; g++)
                ldsm4(bh[g], addrB(base + X_BH, 272, wn * 32 + g * 16, kb, lane));
#pragma unroll
            for (int mf = 0; mf < 2; mf++)
#pragma unroll
                for (int nf = 0; nf < 4; nf++) {
                    int gg = nf >> 1, pp = (nf & 1) * 2;
                    mma_f16(acc[mf][nf], ah[mf], bh[gg][pp], bh[gg][pp + 1]);
                    mma_f16(acc[mf][nf], al[mf], bh[gg][pp], bh[gg][pp + 1]);
                }
        }
        __syncthreads();
    }

    // epilogue: + bias -> g_Xg[row][j]
    const int g = lane >> 2, t2 = (lane & 3) * 2;
#pragma unroll
    for (int mf = 0; mf < 2; mf++) {
        int r0 = m0 + wm * 32 + mf * 16 + g;
#pragma unroll
        for (int nf = 0; nf < 4; nf++) {
            int j0 = n0 + wn * 32 + nf * 8 + t2;
            float2 bi = *(const float2*)&g_bias[j0];
            float2 v0 = {acc[mf][nf][0] + bi.x, acc[mf][nf][1] + bi.y};
            float2 v1 = {acc[mf][nf][2] + bi.x, acc[mf][nf][3] + bi.y};
            *(float2*)&g_Xg[(size_t)r0 * 4096 + j0] = v0;
            *(float2*)&g_Xg[(size_t)(r0 + 8) * 4096 + j0] = v1;
        }
    }
}

// ---------------- persistent recurrent scan ----------------
// 128 CTAs: ct = bx>>2 (j-tile of 128), ks = bx&3 (K slice of 256).
// Wh slice (single fp16) resident in smem all 512 steps. CTA tile m64(b) x n128(j),
// 8 warps (2m x 4n), warp m32n32, 16 k-steps, SINGLE pass (h single fp16).
__global__ __launch_bounds__(256, 1) void lstm_scan(float* __restrict__ out) {
    extern __shared__ char smraw[];
    uint32_t base = smem_u32(smraw);
    char* sm = smraw;
    const int tid = threadIdx.x, lane = tid & 31, wid = tid >> 5;
    const int wm = wid & 1, wn = wid >> 1;
    const int bx = blockIdx.x, ct = bx >> 2, ks = bx & 3;

    // resident Wh slice: cols j [ct*128,+128), k [ks*256,+256)
#pragma unroll
    for (int r16 = 0; r16 < 16; r16++) {
        int i = tid + r16 * 256;             // 0..4095
        int r = i >> 5, c = i & 31;
        size_t src = (size_t)(ct * 128 + r) * 1024 + ks * 256 + c * 8;
        uint32_t dst = (uint32_t)(r * 528 + c * 16);
        *(uint4*)(sm + S_WH + dst) = *(const uint4*)(g_Wh + src);
    }
    __syncthreads();

    const int g = lane >> 2, t2 = (lane & 3) * 2;
    unsigned int nbar = 0;

    for (int t = 0; t < T_STEPS; t++) {
        const int cur = t & 1;
        const __half* __restrict__ hh = g_Hhi[cur];

        // stage h tile [64 b][256 k]
#pragma unroll
        for (int r8 = 0; r8 < 8; r8++) {
            int i = tid + r8 * 256;          // 0..2047
            int r = i >> 5, c = i & 31;
            size_t src = (size_t)r * 1024 + ks * 256 + c * 8;
            uint32_t dst = (uint32_t)(r * 528 + c * 16);
            *(uint4*)(sm + S_AHI + dst) = *(const uint4*)(hh + src);
        }
        __syncthreads();

        float acc[2][4][4];
#pragma unroll
        for (int a = 0; a < 2; a++)
#pragma unroll
            for (int b = 0; b < 4; b++)
#pragma unroll
                for (int c = 0; c < 4; c++) acc[a][b][c] = 0.f;

        for (int kk = 0; kk < 16; kk++) {
            int kb = kk * 32;
            uint32_t ah[2][4], bh[2][4];
#pragma unroll
            for (int mf = 0; mf < 2; mf++)
                ldsm4(ah[mf], addrA(base + S_AHI, 528, wm * 32 + mf * 16, kb, lane));
#pragma unroll
            for (int gg = 0; gg < 2; gg++)
                ldsm4(bh[gg], addrB(base + S_WH, 528, wn * 32 + gg * 16, kb, lane));
#pragma unroll
            for (int mf = 0; mf < 2; mf++)
#pragma unroll
                for (int nf = 0; nf < 4; nf++) {
                    int gg = nf >> 1, pp = (nf & 1) * 2;
                    mma_f16(acc[mf][nf], ah[mf], bh[gg][pp], bh[gg][pp + 1]);
                }
        }

        // write partials: g_part[ks][b][j]
#pragma unroll
        for (int mf = 0; mf < 2; mf++) {
            int b0 = wm * 32 + mf * 16 + g;
#pragma unroll
            for (int nf = 0; nf < 4; nf++) {
                int j0 = ct * 128 + wn * 32 + nf * 8 + t2;
                *(float2*)&g_part[(size_t)(ks * 64 + b0) * 4096 + j0] =
                    make_float2(acc[mf][nf][0], acc[mf][nf][1]);
                *(float2*)&g_part[(size_t)(ks * 64 + b0 + 8) * 4096 + j0] =
                    make_float2(acc[mf][nf][2], acc[mf][nf][3]);
            }
        }

        bar_arrive();
        // prefetch phase-2 operands in the barrier gap (Xg const; c thread-owned)
        float pxg[2][4], pc[2];
        int pidx[2];
#pragma unroll
        for (int r2 = 0; r2 < 2; r2++) {
            int idx = bx * 512 + r2 * 256 + tid;
            pidx[r2] = idx;
            int b = idx >> 10, l = idx & 1023;
            const float* xg = g_Xg + (size_t)(t * 64 + b) * 4096 + l;
            pxg[r2][0] = xg[0];
            pxg[r2][1] = xg[1024];
            pxg[r2][2] = xg[2048];
            pxg[r2][3] = xg[3072];
            pc[r2] = g_c[idx];
        }
        bar_wait(++nbar * NBLK);

        // phase 2: reduce partials + Xg, LSTM pointwise update
#pragma unroll
        for (int r2 = 0; r2 < 2; r2++) {
            int idx = pidx[r2];
            int b = idx >> 10, l = idx & 1023;
            int gidx = (b << 12) + l;
            float gf = pxg[r2][0], gi = pxg[r2][1], go = pxg[r2][2], gg2 = pxg[r2][3];
#pragma unroll
            for (int s = 0; s < 4; s++) {
                const float* p = g_part + (size_t)s * 262144 + gidx;
                gf += p[0];
                gi += p[1024];
                go += p[2048];
                gg2 += p[3072];
            }

            float f = sigm_f(gf);
            float i = sigm_f(gi);
            float o = sigm_f(go);
            float gv = tanh_f(gg2);

            float c = fmaf(f, pc[r2], i * gv);
            float hn = o * tanh_f(c);

            g_c[idx] = c;
            out[(size_t)t * BL + idx] = hn;
            g_Hhi[cur ^ 1][idx] = __float2half(hn);
        }

        bar_arrive();
        bar_wait(++nbar * NBLK);
    }
}

// ---------------- launch ----------------
extern "C" void kernel_launch(void* const* d_in, const int* in_sizes, int n_in,
                              void* d_out, int out_size) {
    const float* x  = (const float*)d_in[0];
    const float* Wf = (const float*)d_in[1];
    const float* bf = (const float*)d_in[2];
    const float* Wi = (const float*)d_in[3];
    const float* bi = (const float*)d_in[4];
    const float* Wo = (const float*)d_in[5];
    const float* bo = (const float*)d_in[6];
    const float* Wg = (const float*)d_in[7];
    const float* bg = (const float*)d_in[8];
    float* out = (float*)d_out;

    cudaFuncSetAttribute(gemm_x, cudaFuncAttributeMaxDynamicSharedMemorySize, GX_SMEM);
    cudaFuncSetAttribute(lstm_scan, cudaFuncAttributeMaxDynamicSharedMemorySize, SCAN_SMEM);

    prep_weights<<<512, 256>>>(Wf, Wi, Wo, Wg, bf, bi, bo, bg);
    split_x<<<1024, 256>>>(x);
    init_state<<<256, 256>>>();
    gemm_x<<<dim3(32, 256), 512, GX_SMEM>>>();
    lstm_scan<<<NBLK, 256, SCAN_SMEM>>>(out);
}